// round 1
// baseline (speedup 1.0000x reference)
#include <cuda_runtime.h>

// Retraction_49271864820311: out = PV (PV^T PV)^{-1/2}, PV = inputs - lr*grad
// per-batch PV is [D=256, K=32]. One CTA (256 threads) per batch.
//
// G^{-1/2} via Z-only Newton-Schulz on A = G/c (c = Gershgorin bound):
//   Z1 = 1.5 I - 0.5 A          (fused iteration 0, since Z0 = I)
//   repeat: S = Z*Z ; M = 1.5I - 0.5*(A*S) ; Z = M*Z
// All iterates are symmetric polynomials in A -> symmetric; we exploit this to
// read "columns as rows" and store transposed for conflict-free shared access.

namespace {

constexpr int D = 256;
constexpr int K = 32;
constexpr int TPB = 256;
constexpr int NS_ITERS = 9;   // includes fused iteration 0

// C = X*Y for (near-)symmetric commuting X,Y. Warp w computes columns 4w..4w+3,
// lane l sweeps rows. Uses X symmetry: X[l][k] read as X[k][l] (vector load,
// conflict-free), Y row chunk as uniform float4 broadcast. Result stored
// transposed (== C by symmetry), also conflict-free.
template <bool FUSE_M>
__device__ __forceinline__ void mm32(const float* __restrict__ X,
                                     const float* __restrict__ Y,
                                     float* __restrict__ C,
                                     int w, int l)
{
    const int j0 = w * 4;
    float c0 = 0.f, c1 = 0.f, c2 = 0.f, c3 = 0.f;
#pragma unroll
    for (int k = 0; k < K; ++k) {
        const float  xv = X[k * K + l];
        const float4 y4 = *reinterpret_cast<const float4*>(Y + k * K + j0);
        c0 = fmaf(xv, y4.x, c0);
        c1 = fmaf(xv, y4.y, c1);
        c2 = fmaf(xv, y4.z, c2);
        c3 = fmaf(xv, y4.w, c3);
    }
    if (FUSE_M) {
        c0 = ((j0 + 0) == l ? 1.5f : 0.f) - 0.5f * c0;
        c1 = ((j0 + 1) == l ? 1.5f : 0.f) - 0.5f * c1;
        c2 = ((j0 + 2) == l ? 1.5f : 0.f) - 0.5f * c2;
        c3 = ((j0 + 3) == l ? 1.5f : 0.f) - 0.5f * c3;
    }
    C[(j0 + 0) * K + l] = c0;
    C[(j0 + 1) * K + l] = c1;
    C[(j0 + 2) * K + l] = c2;
    C[(j0 + 3) * K + l] = c3;
}

__global__ void __launch_bounds__(TPB, 2)
retraction_kernel(const float* __restrict__ x,
                  const float* __restrict__ g,
                  const float* __restrict__ lr_ptr,
                  float* __restrict__ out)
{
    __shared__ float s_pv[D * K];   // 32 KB, row-major stride 32
    __shared__ float s_A[K * K];    // G / c
    __shared__ float s_Z[K * K];
    __shared__ float s_S[K * K];    // scratch (Z^2 / Znew) + scalar slot
    __shared__ float s_M[K * K];

    const int tid  = threadIdx.x;
    const int lane = tid & 31;
    const int w    = tid >> 5;
    const long long base = (long long)blockIdx.x * (D * K);
    const float lr = __ldg(lr_ptr);

    // ---------------- Phase 1: PV row `tid` -> registers + shared ----------
    float pv[K];
    {
        const float4* x4 = reinterpret_cast<const float4*>(x + base) + tid * (K / 4);
        const float4* g4 = reinterpret_cast<const float4*>(g + base) + tid * (K / 4);
#pragma unroll
        for (int q = 0; q < K / 4; ++q) {
            const float4 a = x4[q];
            const float4 b = g4[q];
            pv[4 * q + 0] = fmaf(-lr, b.x, a.x);
            pv[4 * q + 1] = fmaf(-lr, b.y, a.y);
            pv[4 * q + 2] = fmaf(-lr, b.z, a.z);
            pv[4 * q + 3] = fmaf(-lr, b.w, a.w);
        }
        float4* row = reinterpret_cast<float4*>(s_pv + tid * K);
#pragma unroll
        for (int q = 0; q < K / 4; ++q)
            row[q] = make_float4(pv[4 * q + 0], pv[4 * q + 1],
                                 pv[4 * q + 2], pv[4 * q + 3]);
    }
    __syncthreads();

    // ---------------- Phase 2: G = PV^T PV (2x2 register tiles) ------------
    {
        const int ti = tid >> 4;   // 0..15 -> rows 2ti,2ti+1 of G
        const int tj = tid & 15;   // 0..15 -> cols 2tj,2tj+1 of G
        float c00 = 0.f, c01 = 0.f, c10 = 0.f, c11 = 0.f;
#pragma unroll 8
        for (int d = 0; d < D; ++d) {
            const float* r = s_pv + d * K;
            const float2 a = *reinterpret_cast<const float2*>(r + 2 * ti);
            const float2 b = *reinterpret_cast<const float2*>(r + 2 * tj);
            c00 = fmaf(a.x, b.x, c00);
            c01 = fmaf(a.x, b.y, c01);
            c10 = fmaf(a.y, b.x, c10);
            c11 = fmaf(a.y, b.y, c11);
        }
        s_A[(2 * ti + 0) * K + 2 * tj + 0] = c00;
        s_A[(2 * ti + 0) * K + 2 * tj + 1] = c01;
        s_A[(2 * ti + 1) * K + 2 * tj + 0] = c10;
        s_A[(2 * ti + 1) * K + 2 * tj + 1] = c11;
    }
    __syncthreads();

    // ---------------- Phase 3: Gershgorin scale c ---------------------------
    // G symmetric -> row sum == column sum; column access is conflict-free.
    if (tid < 32) {
        float s = 0.f;
#pragma unroll
        for (int j = 0; j < K; ++j) s += fabsf(s_A[j * K + tid]);
#pragma unroll
        for (int o = 16; o > 0; o >>= 1)
            s = fmaxf(s, __shfl_xor_sync(0xffffffffu, s, o));
        if (tid == 0) s_S[0] = s;
    }
    __syncthreads();
    const float cmax = s_S[0];
    const float invc = 1.0f / cmax;
    const float rsc  = rsqrtf(cmax);   // P = Z_final * c^{-1/2}
    __syncthreads();

    // ---------------- Phase 4: A = G/c ; Z = 1.5I - 0.5A (fused iter 0) ----
    {
        float4* pG = reinterpret_cast<float4*>(s_A);
        float4 v = pG[tid];
        v.x *= invc; v.y *= invc; v.z *= invc; v.w *= invc;
        pG[tid] = v;
        const int idx = tid * 4;
        const int i  = idx >> 5;     // row
        const int jb = idx & 31;     // first col of the float4
        float4 z;
        z.x = (i == jb + 0 ? 1.5f : 0.f) - 0.5f * v.x;
        z.y = (i == jb + 1 ? 1.5f : 0.f) - 0.5f * v.y;
        z.z = (i == jb + 2 ? 1.5f : 0.f) - 0.5f * v.z;
        z.w = (i == jb + 3 ? 1.5f : 0.f) - 0.5f * v.w;
        reinterpret_cast<float4*>(s_Z)[tid] = z;
    }
    __syncthreads();

    // ---------------- Phase 5: Newton-Schulz iterations ---------------------
    float* Zc = s_Z;
    float* Sc = s_S;
    for (int it = 1; it < NS_ITERS; ++it) {
        mm32<false>(Zc, Zc, Sc, w, lane);          // S = Z*Z
        __syncthreads();
        mm32<true >(s_A, Sc, s_M, w, lane);        // M = 1.5I - 0.5*A*S
        __syncthreads();
        mm32<false>(s_M, Zc, Sc, w, lane);         // Znew = M*Z  (S is dead)
        __syncthreads();
        float* t = Zc; Zc = Sc; Sc = t;
    }

    // ---------------- Phase 6: out = PV * Z * c^{-1/2} ----------------------
    float acc[K];
#pragma unroll
    for (int i = 0; i < K; ++i) acc[i] = 0.f;
#pragma unroll
    for (int j = 0; j < K; ++j) {
        const float a = pv[j];
        const float* zr = Zc + j * K;
#pragma unroll
        for (int q = 0; q < K / 4; ++q) {
            const float4 z = *reinterpret_cast<const float4*>(zr + 4 * q);
            acc[4 * q + 0] = fmaf(a, z.x, acc[4 * q + 0]);
            acc[4 * q + 1] = fmaf(a, z.y, acc[4 * q + 1]);
            acc[4 * q + 2] = fmaf(a, z.z, acc[4 * q + 2]);
            acc[4 * q + 3] = fmaf(a, z.w, acc[4 * q + 3]);
        }
    }
    float4* o4 = reinterpret_cast<float4*>(out + base + tid * K);
#pragma unroll
    for (int q = 0; q < K / 4; ++q)
        o4[q] = make_float4(acc[4 * q + 0] * rsc, acc[4 * q + 1] * rsc,
                            acc[4 * q + 2] * rsc, acc[4 * q + 3] * rsc);
}

} // namespace

extern "C" void kernel_launch(void* const* d_in, const int* in_sizes, int n_in,
                              void* d_out, int out_size)
{
    const float* x  = (const float*)d_in[0];
    const float* g  = (const float*)d_in[1];
    const float* lr = (const float*)d_in[2];
    float* out = (float*)d_out;
    const int n_batches = out_size / (D * K);   // 8192
    retraction_kernel<<<n_batches, TPB>>>(x, g, lr, out);
}

// round 2
// speedup vs baseline: 1.3146x; 1.3146x over previous
#include <cuda_runtime.h>

// Retraction: out = PV (PV^T PV)^{-1/2}, PV = inputs - lr*grad, per batch
// PV is [D=256, K=32]. One CTA (256 threads) per batch.
//
// G^{-1/2} via Z-only Newton-Schulz on A = G * (2.2/c), c = Gershgorin bound.
// The 2.2 rescale recenters eig(A) toward 1 (eig <= 2.2 < 3, still convergent),
// cutting iterations from 9 to 6 (1 fused + 5 full = 15 32x32 matmuls).

namespace {

constexpr int D = 256;
constexpr int K = 32;
constexpr int TPB = 256;
constexpr int NS_ITERS = 6;          // total z-updates incl. fused iter 0
constexpr float SCALE_BOOST = 2.2f;  // eig(A) in (0, 2.2]; NS converges for (0,3)

// C = X*Y for symmetric commuting X,Y (all NS iterates are polynomials in A).
// Warp w computes columns 4w..4w+3, lane l sweeps rows. X[l][k] read as
// X[k][l] (vector across lanes, conflict-free), Y row chunk broadcast.
// Result stored transposed (== C by symmetry), conflict-free.
template <bool FUSE_M>
__device__ __forceinline__ void mm32(const float* __restrict__ X,
                                     const float* __restrict__ Y,
                                     float* __restrict__ C,
                                     int w, int l)
{
    const int j0 = w * 4;
    float c0 = 0.f, c1 = 0.f, c2 = 0.f, c3 = 0.f;
#pragma unroll
    for (int k = 0; k < K; ++k) {
        const float  xv = X[k * K + l];
        const float4 y4 = *reinterpret_cast<const float4*>(Y + k * K + j0);
        c0 = fmaf(xv, y4.x, c0);
        c1 = fmaf(xv, y4.y, c1);
        c2 = fmaf(xv, y4.z, c2);
        c3 = fmaf(xv, y4.w, c3);
    }
    if (FUSE_M) {
        c0 = ((j0 + 0) == l ? 1.5f : 0.f) - 0.5f * c0;
        c1 = ((j0 + 1) == l ? 1.5f : 0.f) - 0.5f * c1;
        c2 = ((j0 + 2) == l ? 1.5f : 0.f) - 0.5f * c2;
        c3 = ((j0 + 3) == l ? 1.5f : 0.f) - 0.5f * c3;
    }
    C[(j0 + 0) * K + l] = c0;
    C[(j0 + 1) * K + l] = c1;
    C[(j0 + 2) * K + l] = c2;
    C[(j0 + 3) * K + l] = c3;
}

__global__ void __launch_bounds__(TPB, 2)
retraction_kernel(const float* __restrict__ x,
                  const float* __restrict__ g,
                  const float* __restrict__ lr_ptr,
                  float* __restrict__ out)
{
    __shared__ float s_pv[D * K];   // 32 KB, row-major stride 32
    __shared__ float s_A[K * K];    // also phase-2 partial buffer 0
    __shared__ float s_Z[K * K];    // partial buffer 1
    __shared__ float s_S[K * K];    // partial buffer 2 (+ scalar slot)
    __shared__ float s_M[K * K];    // partial buffer 3

    const int tid  = threadIdx.x;
    const int lane = tid & 31;
    const int w    = tid >> 5;
    const long long base = (long long)blockIdx.x * (D * K);
    const float lr = __ldg(lr_ptr);

    // ---------------- Phase 1: PV row `tid` -> registers + shared ----------
    float pv[K];
    {
        const float4* x4 = reinterpret_cast<const float4*>(x + base) + tid * (K / 4);
        const float4* g4 = reinterpret_cast<const float4*>(g + base) + tid * (K / 4);
#pragma unroll
        for (int q = 0; q < K / 4; ++q) {
            const float4 a = x4[q];
            const float4 b = g4[q];
            pv[4 * q + 0] = fmaf(-lr, b.x, a.x);
            pv[4 * q + 1] = fmaf(-lr, b.y, a.y);
            pv[4 * q + 2] = fmaf(-lr, b.z, a.z);
            pv[4 * q + 3] = fmaf(-lr, b.w, a.w);
        }
        float4* row = reinterpret_cast<float4*>(s_pv + tid * K);
#pragma unroll
        for (int q = 0; q < K / 4; ++q)
            row[q] = make_float4(pv[4 * q + 0], pv[4 * q + 1],
                                 pv[4 * q + 2], pv[4 * q + 3]);
    }
    __syncthreads();

    // ---------------- Phase 2: G = PV^T PV, 4x4 tiles, 4-way D split --------
    // thread -> (p = d-partition, ti, tj); partials go into the (currently
    // dead) 32x32 matrix buffers; then a vectorized 4-way reduction.
    {
        const int p  = tid >> 6;          // 0..3 : d in [64p, 64p+64)
        const int t  = tid & 63;
        const int ti = t >> 3;            // 0..7 -> rows 4ti..4ti+3
        const int tj = t & 7;             // 0..7 -> cols 4tj..4tj+3
        const int i0 = ti * 4, j0 = tj * 4;

        float a00=0.f,a01=0.f,a02=0.f,a03=0.f;
        float a10=0.f,a11=0.f,a12=0.f,a13=0.f;
        float a20=0.f,a21=0.f,a22=0.f,a23=0.f;
        float a30=0.f,a31=0.f,a32=0.f,a33=0.f;

        const float* pvb = s_pv + p * 64 * K;
#pragma unroll 4
        for (int dd = 0; dd < 64; ++dd) {
            const float* r = pvb + dd * K;
            const float4 a = *reinterpret_cast<const float4*>(r + i0);
            const float4 b = *reinterpret_cast<const float4*>(r + j0);
            a00 = fmaf(a.x, b.x, a00); a01 = fmaf(a.x, b.y, a01);
            a02 = fmaf(a.x, b.z, a02); a03 = fmaf(a.x, b.w, a03);
            a10 = fmaf(a.y, b.x, a10); a11 = fmaf(a.y, b.y, a11);
            a12 = fmaf(a.y, b.z, a12); a13 = fmaf(a.y, b.w, a13);
            a20 = fmaf(a.z, b.x, a20); a21 = fmaf(a.z, b.y, a21);
            a22 = fmaf(a.z, b.z, a22); a23 = fmaf(a.z, b.w, a23);
            a30 = fmaf(a.w, b.x, a30); a31 = fmaf(a.w, b.y, a31);
            a32 = fmaf(a.w, b.z, a32); a33 = fmaf(a.w, b.w, a33);
        }
        float* pb = (p == 0) ? s_A : (p == 1) ? s_Z : (p == 2) ? s_S : s_M;
        *reinterpret_cast<float4*>(pb + (i0 + 0) * K + j0) = make_float4(a00, a01, a02, a03);
        *reinterpret_cast<float4*>(pb + (i0 + 1) * K + j0) = make_float4(a10, a11, a12, a13);
        *reinterpret_cast<float4*>(pb + (i0 + 2) * K + j0) = make_float4(a20, a21, a22, a23);
        *reinterpret_cast<float4*>(pb + (i0 + 3) * K + j0) = make_float4(a30, a31, a32, a33);
    }
    __syncthreads();

    // Reduce the 4 partials into s_A (each thread owns 4 consecutive floats;
    // read/write sets are disjoint across threads -> single sync after).
    {
        const int idx = tid * 4;
        const float4 v0 = *reinterpret_cast<const float4*>(s_A + idx);
        const float4 v1 = *reinterpret_cast<const float4*>(s_Z + idx);
        const float4 v2 = *reinterpret_cast<const float4*>(s_S + idx);
        const float4 v3 = *reinterpret_cast<const float4*>(s_M + idx);
        *reinterpret_cast<float4*>(s_A + idx) =
            make_float4(v0.x + v1.x + v2.x + v3.x,
                        v0.y + v1.y + v2.y + v3.y,
                        v0.z + v1.z + v2.z + v3.z,
                        v0.w + v1.w + v2.w + v3.w);
    }
    __syncthreads();

    // ---------------- Phase 3: Gershgorin scale c ---------------------------
    // G symmetric -> row sum == column sum; column access is conflict-free.
    if (tid < 32) {
        float s = 0.f;
#pragma unroll
        for (int j = 0; j < K; ++j) s += fabsf(s_A[j * K + tid]);
#pragma unroll
        for (int o = 16; o > 0; o >>= 1)
            s = fmaxf(s, __shfl_xor_sync(0xffffffffu, s, o));
        if (tid == 0) s_S[0] = s;
    }
    __syncthreads();
    const float scale = SCALE_BOOST / s_S[0];   // A = scale * G
    const float rsc   = sqrtf(scale);           // P = Z_final * sqrt(scale)
    __syncthreads();

    // ---------------- Phase 4: A = scale*G ; Z = 1.5I - 0.5A (fused iter 0) -
    {
        float4* pG = reinterpret_cast<float4*>(s_A);
        float4 v = pG[tid];
        v.x *= scale; v.y *= scale; v.z *= scale; v.w *= scale;
        pG[tid] = v;
        const int idx = tid * 4;
        const int i  = idx >> 5;     // row
        const int jb = idx & 31;     // first col of the float4
        float4 z;
        z.x = (i == jb + 0 ? 1.5f : 0.f) - 0.5f * v.x;
        z.y = (i == jb + 1 ? 1.5f : 0.f) - 0.5f * v.y;
        z.z = (i == jb + 2 ? 1.5f : 0.f) - 0.5f * v.z;
        z.w = (i == jb + 3 ? 1.5f : 0.f) - 0.5f * v.w;
        reinterpret_cast<float4*>(s_Z)[tid] = z;
    }
    __syncthreads();

    // ---------------- Phase 5: Newton-Schulz iterations ---------------------
    float* Zc = s_Z;
    float* Sc = s_S;
    for (int it = 1; it < NS_ITERS; ++it) {
        mm32<false>(Zc, Zc, Sc, w, lane);          // S = Z*Z
        __syncthreads();
        mm32<true >(s_A, Sc, s_M, w, lane);        // M = 1.5I - 0.5*A*S
        __syncthreads();
        mm32<false>(s_M, Zc, Sc, w, lane);         // Znew = M*Z  (S is dead)
        __syncthreads();
        float* t = Zc; Zc = Sc; Sc = t;
    }

    // ---------------- Phase 6: out = PV * Z * sqrt(scale) -------------------
    float acc[K];
#pragma unroll
    for (int i = 0; i < K; ++i) acc[i] = 0.f;
#pragma unroll
    for (int j = 0; j < K; ++j) {
        const float a = pv[j];
        const float* zr = Zc + j * K;
#pragma unroll
        for (int q = 0; q < K / 4; ++q) {
            const float4 z = *reinterpret_cast<const float4*>(zr + 4 * q);
            acc[4 * q + 0] = fmaf(a, z.x, acc[4 * q + 0]);
            acc[4 * q + 1] = fmaf(a, z.y, acc[4 * q + 1]);
            acc[4 * q + 2] = fmaf(a, z.z, acc[4 * q + 2]);
            acc[4 * q + 3] = fmaf(a, z.w, acc[4 * q + 3]);
        }
    }
    float4* o4 = reinterpret_cast<float4*>(out + base + tid * K);
#pragma unroll
    for (int q = 0; q < K / 4; ++q)
        o4[q] = make_float4(acc[4 * q + 0] * rsc, acc[4 * q + 1] * rsc,
                            acc[4 * q + 2] * rsc, acc[4 * q + 3] * rsc);
}

} // namespace

extern "C" void kernel_launch(void* const* d_in, const int* in_sizes, int n_in,
                              void* d_out, int out_size)
{
    const float* x  = (const float*)d_in[0];
    const float* g  = (const float*)d_in[1];
    const float* lr = (const float*)d_in[2];
    float* out = (float*)d_out;
    const int n_batches = out_size / (D * K);   // 8192
    retraction_kernel<<<n_batches, TPB>>>(x, g, lr, out);
}